// round 2
// baseline (speedup 1.0000x reference)
#include <cuda_runtime.h>
#include <math.h>

// ---------------- scratch (no allocations allowed) ----------------
__device__ float g_Q[4096 * 2048];   // [B*T, 16*128]
__device__ float g_K[4096 * 512];    // [B*T, 4*128]
__device__ float g_V[4096 * 512];
__device__ float g_ctx[4096 * 2048];

// ---------------- generic SGEMM: C[M,N] = A[M,K] * B[N,K]^T ----------------
#define BM 128
#define BN 128
#define BKK 16

__global__ __launch_bounds__(256) void sgemm_nt(const float* __restrict__ A,
                                                const float* __restrict__ B,
                                                float* __restrict__ C,
                                                int M, int N, int K)
{
    __shared__ float As[BKK][BM + 4];
    __shared__ float Bs[BKK][BN + 4];
    int tid = threadIdx.x;
    int tx = tid & 15, ty = tid >> 4;
    int rowC = blockIdx.y * BM;
    int colC = blockIdx.x * BN;

    float acc[8][8];
#pragma unroll
    for (int i = 0; i < 8; i++)
#pragma unroll
        for (int j = 0; j < 8; j++) acc[i][j] = 0.f;

    int lr = tid >> 2;            // 0..63
    int lc = (tid & 3) * 4;       // 0,4,8,12
    const float* Ag = A + (size_t)(rowC + lr) * K + lc;
    const float* Bg = B + (size_t)(colC + lr) * K + lc;

    for (int k0 = 0; k0 < K; k0 += BKK) {
#pragma unroll
        for (int r = 0; r < BM; r += 64) {
            float4 v = *(const float4*)(Ag + (size_t)r * K + k0);
            As[lc + 0][lr + r] = v.x; As[lc + 1][lr + r] = v.y;
            As[lc + 2][lr + r] = v.z; As[lc + 3][lr + r] = v.w;
        }
#pragma unroll
        for (int r = 0; r < BN; r += 64) {
            float4 v = *(const float4*)(Bg + (size_t)r * K + k0);
            Bs[lc + 0][lr + r] = v.x; Bs[lc + 1][lr + r] = v.y;
            Bs[lc + 2][lr + r] = v.z; Bs[lc + 3][lr + r] = v.w;
        }
        __syncthreads();
#pragma unroll
        for (int k = 0; k < BKK; k++) {
            float ra[8], rb[8];
            *(float4*)&ra[0] = *(const float4*)&As[k][ty * 8];
            *(float4*)&ra[4] = *(const float4*)&As[k][ty * 8 + 4];
            *(float4*)&rb[0] = *(const float4*)&Bs[k][tx * 8];
            *(float4*)&rb[4] = *(const float4*)&Bs[k][tx * 8 + 4];
#pragma unroll
            for (int i = 0; i < 8; i++)
#pragma unroll
                for (int j = 0; j < 8; j++)
                    acc[i][j] = fmaf(ra[i], rb[j], acc[i][j]);
        }
        __syncthreads();
    }
#pragma unroll
    for (int i = 0; i < 8; i++) {
        float* Cp = C + (size_t)(rowC + ty * 8 + i) * N + colC + tx * 8;
        *(float4*)Cp       = make_float4(acc[i][0], acc[i][1], acc[i][2], acc[i][3]);
        *(float4*)(Cp + 4) = make_float4(acc[i][4], acc[i][5], acc[i][6], acc[i][7]);
    }
}

// ---------------- fused QKV projection (one launch, 768 CTAs) ----------------
__global__ __launch_bounds__(256) void qkv_gemm(const float* __restrict__ x,
                                                const float* __restrict__ wq,
                                                const float* __restrict__ wk,
                                                const float* __restrict__ wv,
                                                float* __restrict__ Qo,
                                                float* __restrict__ Ko,
                                                float* __restrict__ Vo)
{
    const int K = 2048;
    __shared__ float As[BKK][BM + 4];
    __shared__ float Bs[BKK][BN + 4];

    int bx = blockIdx.x;
    const float* B; float* C; int ldc; int colC;
    if (bx < 16)      { B = wq; C = Qo; ldc = 2048; colC = bx * 128; }
    else if (bx < 20) { B = wk; C = Ko; ldc = 512;  colC = (bx - 16) * 128; }
    else              { B = wv; C = Vo; ldc = 512;  colC = (bx - 20) * 128; }

    int tid = threadIdx.x;
    int tx = tid & 15, ty = tid >> 4;
    int rowC = blockIdx.y * BM;

    float acc[8][8];
#pragma unroll
    for (int i = 0; i < 8; i++)
#pragma unroll
        for (int j = 0; j < 8; j++) acc[i][j] = 0.f;

    int lr = tid >> 2;
    int lc = (tid & 3) * 4;
    const float* Ag = x + (size_t)(rowC + lr) * K + lc;
    const float* Bg = B + (size_t)(colC + lr) * K + lc;

    for (int k0 = 0; k0 < K; k0 += BKK) {
#pragma unroll
        for (int r = 0; r < BM; r += 64) {
            float4 v = *(const float4*)(Ag + (size_t)r * K + k0);
            As[lc + 0][lr + r] = v.x; As[lc + 1][lr + r] = v.y;
            As[lc + 2][lr + r] = v.z; As[lc + 3][lr + r] = v.w;
        }
#pragma unroll
        for (int r = 0; r < BN; r += 64) {
            float4 v = *(const float4*)(Bg + (size_t)r * K + k0);
            Bs[lc + 0][lr + r] = v.x; Bs[lc + 1][lr + r] = v.y;
            Bs[lc + 2][lr + r] = v.z; Bs[lc + 3][lr + r] = v.w;
        }
        __syncthreads();
#pragma unroll
        for (int k = 0; k < BKK; k++) {
            float ra[8], rb[8];
            *(float4*)&ra[0] = *(const float4*)&As[k][ty * 8];
            *(float4*)&ra[4] = *(const float4*)&As[k][ty * 8 + 4];
            *(float4*)&rb[0] = *(const float4*)&Bs[k][tx * 8];
            *(float4*)&rb[4] = *(const float4*)&Bs[k][tx * 8 + 4];
#pragma unroll
            for (int i = 0; i < 8; i++)
#pragma unroll
                for (int j = 0; j < 8; j++)
                    acc[i][j] = fmaf(ra[i], rb[j], acc[i][j]);
        }
        __syncthreads();
    }
#pragma unroll
    for (int i = 0; i < 8; i++) {
        float* Cp = C + (size_t)(rowC + ty * 8 + i) * ldc + colC + tx * 8;
        *(float4*)Cp       = make_float4(acc[i][0], acc[i][1], acc[i][2], acc[i][3]);
        *(float4*)(Cp + 4) = make_float4(acc[i][4], acc[i][5], acc[i][6], acc[i][7]);
    }
}

// ---------------- RoPE (in-place on Q or K) ----------------
__global__ __launch_bounds__(256) void rope_kernel(float* __restrict__ data,
                                                   const int* __restrict__ positions,
                                                   int heads)
{
    int idx = blockIdx.x * 256 + threadIdx.x;
    int j = idx & 63;
    int row = idx >> 6;                 // (bt*heads + h)
    int bt = row / heads;
    float pos = (float)positions[bt];
    float inv_freq = powf(10000.0f, -(float)j * (1.0f / 64.0f));
    float ang = pos * inv_freq;
    float s, c;
    sincosf(ang, &s, &c);
    float* p = data + (size_t)row * 128;
    float x1 = p[j], x2 = p[j + 64];
    p[j]      = x1 * c - x2 * s;
    p[j + 64] = x1 * s + x2 * c;
}

// ---------------- flash attention (causal, GQA 4:1) ----------------
// smem: Qt[128][64] swizzled, Kt[128][64] swizzled, Vs[64][128], Ps[64][65]
#define FA_SMEM ((128 * 64 + 128 * 64 + 64 * 128 + 64 * 65) * 4)

__device__ __forceinline__ int swz4(int k, int g) {
    // transposed [k][r] layout, r grouped by 4; group XOR-swizzled by (k>>2)&15
    return k * 64 + (((g) ^ ((k >> 2) & 15)) << 2);
}

__global__ __launch_bounds__(256) void flash_attn(const float* __restrict__ Q,
                                                  const float* __restrict__ K,
                                                  const float* __restrict__ V,
                                                  float* __restrict__ ctx)
{
    const int T = 2048, HD = 128;
    extern __shared__ float sm[];
    float* Qt = sm;                  // [128][64] swizzled
    float* Kt = Qt + 128 * 64;       // [128][64] swizzled
    float* Vs = Kt + 128 * 64;       // [64][128]
    float* Ps = Vs + 64 * 128;       // [64][65]

    int qt = blockIdx.x, h = blockIdx.y, b = blockIdx.z;
    int kvh = h >> 2;
    int tid = threadIdx.x;
    int tx = tid & 15, ty = tid >> 4;

    // load Q tile, transposed + swizzled
    const float* Qg = Q + ((size_t)(b * T + qt * 64)) * 2048 + h * HD;
    for (int i = tid; i < 64 * 32; i += 256) {
        int r = i >> 5;
        int c4 = (i & 31) << 2;
        float4 v = *(const float4*)(Qg + (size_t)r * 2048 + c4);
        int base = (((r >> 2) ^ ((c4 >> 2) & 15)) << 2) + (r & 3);
        Qt[(c4 + 0) * 64 + base] = v.x;
        Qt[(c4 + 1) * 64 + base] = v.y;
        Qt[(c4 + 2) * 64 + base] = v.z;
        Qt[(c4 + 3) * 64 + base] = v.w;
    }

    float m[4], l[4], o[4][8];
#pragma unroll
    for (int i = 0; i < 4; i++) {
        m[i] = -INFINITY; l[i] = 0.f;
#pragma unroll
        for (int d = 0; d < 8; d++) o[i][d] = 0.f;
    }

    const float scale = 0.08838834764831845f; // 1/sqrt(128)

    for (int kt = 0; kt <= qt; kt++) {
        __syncthreads();   // protects Kt/Vs/Ps reuse & Qt readiness
        const float* Kg = K + ((size_t)(b * T + kt * 64)) * 512 + kvh * HD;
        const float* Vg = V + ((size_t)(b * T + kt * 64)) * 512 + kvh * HD;
        for (int i = tid; i < 64 * 32; i += 256) {
            int r = i >> 5;
            int c4 = (i & 31) << 2;
            float4 kv = *(const float4*)(Kg + (size_t)r * 512 + c4);
            int base = (((r >> 2) ^ ((c4 >> 2) & 15)) << 2) + (r & 3);
            Kt[(c4 + 0) * 64 + base] = kv.x;
            Kt[(c4 + 1) * 64 + base] = kv.y;
            Kt[(c4 + 2) * 64 + base] = kv.z;
            Kt[(c4 + 3) * 64 + base] = kv.w;
            *(float4*)(Vs + r * 128 + c4) = *(const float4*)(Vg + (size_t)r * 512 + c4);
        }
        __syncthreads();

        // S = Q K^T  (4x4 per thread)
        float s[4][4];
#pragma unroll
        for (int i = 0; i < 4; i++)
#pragma unroll
            for (int j = 0; j < 4; j++) s[i][j] = 0.f;

#pragma unroll 4
        for (int k = 0; k < HD; k++) {
            int sw = (k >> 2) & 15;
            float4 a  = *(const float4*)&Qt[k * 64 + ((ty ^ sw) << 2)];
            float4 bb = *(const float4*)&Kt[k * 64 + ((tx ^ sw) << 2)];
            float av[4] = {a.x, a.y, a.z, a.w};
            float bv[4] = {bb.x, bb.y, bb.z, bb.w};
#pragma unroll
            for (int i = 0; i < 4; i++)
#pragma unroll
                for (int j = 0; j < 4; j++)
                    s[i][j] = fmaf(av[i], bv[j], s[i][j]);
        }

        // scale + causal mask (diagonal tile only)
        if (kt == qt) {
#pragma unroll
            for (int i = 0; i < 4; i++)
#pragma unroll
                for (int j = 0; j < 4; j++) {
                    int qi = ty * 4 + i, kj = tx * 4 + j;
                    s[i][j] = (kj <= qi) ? s[i][j] * scale : -1e9f;
                }
        } else {
#pragma unroll
            for (int i = 0; i < 4; i++)
#pragma unroll
                for (int j = 0; j < 4; j++) s[i][j] *= scale;
        }

        // online softmax (row reductions across the 16 tx lanes)
#pragma unroll
        for (int i = 0; i < 4; i++) {
            float mt = fmaxf(fmaxf(s[i][0], s[i][1]), fmaxf(s[i][2], s[i][3]));
#pragma unroll
            for (int off = 8; off >= 1; off >>= 1)
                mt = fmaxf(mt, __shfl_xor_sync(0xffffffffu, mt, off));
            float mnew = fmaxf(m[i], mt);
            float corr = __expf(m[i] - mnew);
            float rs = 0.f;
#pragma unroll
            for (int j = 0; j < 4; j++) {
                float p = __expf(s[i][j] - mnew);
                s[i][j] = p;
                rs += p;
            }
#pragma unroll
            for (int off = 8; off >= 1; off >>= 1)
                rs += __shfl_xor_sync(0xffffffffu, rs, off);
            l[i] = l[i] * corr + rs;
            m[i] = mnew;
#pragma unroll
            for (int d = 0; d < 8; d++) o[i][d] *= corr;
        }

        // stash P
#pragma unroll
        for (int i = 0; i < 4; i++)
#pragma unroll
            for (int j = 0; j < 4; j++)
                Ps[(ty * 4 + i) * 65 + tx * 4 + j] = s[i][j];
        __syncthreads();

        // O += P @ V  (rows ty*4+i, cols tx*8..tx*8+7)
#pragma unroll 8
        for (int j = 0; j < 64; j++) {
            float4 v0 = *(const float4*)(Vs + j * 128 + tx * 8);
            float4 v1 = *(const float4*)(Vs + j * 128 + tx * 8 + 4);
#pragma unroll
            for (int i = 0; i < 4; i++) {
                float p = Ps[(ty * 4 + i) * 65 + j];
                o[i][0] = fmaf(p, v0.x, o[i][0]);
                o[i][1] = fmaf(p, v0.y, o[i][1]);
                o[i][2] = fmaf(p, v0.z, o[i][2]);
                o[i][3] = fmaf(p, v0.w, o[i][3]);
                o[i][4] = fmaf(p, v1.x, o[i][4]);
                o[i][5] = fmaf(p, v1.y, o[i][5]);
                o[i][6] = fmaf(p, v1.z, o[i][6]);
                o[i][7] = fmaf(p, v1.w, o[i][7]);
            }
        }
    }

    // epilogue: ctx[b,t,h,d] = O / l
    float* Cg = ctx + ((size_t)(b * T + qt * 64)) * 2048 + h * HD;
#pragma unroll
    for (int i = 0; i < 4; i++) {
        float inv = 1.0f / l[i];
        int r = ty * 4 + i;
        *(float4*)(Cg + (size_t)r * 2048 + tx * 8) =
            make_float4(o[i][0] * inv, o[i][1] * inv, o[i][2] * inv, o[i][3] * inv);
        *(float4*)(Cg + (size_t)r * 2048 + tx * 8 + 4) =
            make_float4(o[i][4] * inv, o[i][5] * inv, o[i][6] * inv, o[i][7] * inv);
    }
}

// ---------------- launch ----------------
extern "C" void kernel_launch(void* const* d_in, const int* in_sizes, int n_in,
                              void* d_out, int out_size)
{
    const float* x  = (const float*)d_in[0];
    const int*   pos = (const int*)d_in[1];
    const float* wq = (const float*)d_in[2];
    const float* wk = (const float*)d_in[3];
    const float* wv = (const float*)d_in[4];
    const float* wo = (const float*)d_in[5];
    float* out = (float*)d_out;

    float *Qp, *Kp, *Vp, *Cp;
    cudaGetSymbolAddress((void**)&Qp, g_Q);
    cudaGetSymbolAddress((void**)&Kp, g_K);
    cudaGetSymbolAddress((void**)&Vp, g_V);
    cudaGetSymbolAddress((void**)&Cp, g_ctx);

    cudaFuncSetAttribute(flash_attn, cudaFuncAttributeMaxDynamicSharedMemorySize, FA_SMEM);

    // QKV projections (fused): grid.x = 16(Q) + 4(K) + 4(V)
    qkv_gemm<<<dim3(24, 32), 256>>>(x, wq, wk, wv, Qp, Kp, Vp);

    // RoPE on Q (16 heads) and K (4 heads)
    rope_kernel<<<(4096 * 16 * 64) / 256, 256>>>(Qp, pos, 16);
    rope_kernel<<<(4096 * 4 * 64) / 256, 256>>>(Kp, pos, 4);

    // causal GQA attention
    flash_attn<<<dim3(32, 16, 2), 256, FA_SMEM>>>(Qp, Kp, Vp, Cp);

    // output projection
    sgemm_nt<<<dim3(16, 32), 256>>>(Cp, wo, out, 4096, 2048, 2048);
}